// round 4
// baseline (speedup 1.0000x reference)
#include <cuda_runtime.h>

#define B 32
#define N 2048
#define C 64
#define R 32
#define K 64

__device__ float g_pv[B * N];     // dense top-k vector per batch
__device__ float g_vals[B * K];
__device__ int   g_idx[B * K];

// total-order "a before b" in descending-value, ascending-index order
__device__ __forceinline__ bool tfirst(float va, int ia, float vb, int ib) {
    return (va > vb) || (va == vb && ia < ib);
}

// shuffle compare-exchange; partner differs in lane bit j
__device__ __forceinline__ void cmpx(float& v, int& i, int j, bool desc) {
    float ov = __shfl_xor_sync(0xffffffffu, v, j);
    int   oi = __shfl_xor_sync(0xffffffffu, i, j);
    bool lower = ((threadIdx.x & 31 & j) == 0);
    bool mine_first = tfirst(v, i, ov, oi);
    if (mine_first != (lower == desc)) { v = ov; i = oi; }
}

// ---------------------------------------------------------------------------
// Kernel 1: warp-register bitonic top-K + pv scatter. One block per batch row.
// ---------------------------------------------------------------------------
__global__ __launch_bounds__(1024)
void topk_kernel(const float* __restrict__ acc, float* __restrict__ out) {
    __shared__ float sv[N];
    __shared__ int   si[N];
    const int b    = blockIdx.x;
    const int tid  = threadIdx.x;
    const int lane = tid & 31;
    const int w    = tid >> 5;           // warp 0..31

    // zero pv row (independent of the sort)
    g_pv[b * N + tid] = 0.0f;
    g_pv[b * N + tid + 1024] = 0.0f;

    // ---- load chunk w: elements e0=lane, e1=lane+32 of a 64-elem list ----
    const float* row = acc + b * N;
    float v0 = row[w * 64 + lane];        int i0 = w * 64 + lane;
    float v1 = row[w * 64 + 32 + lane];   int i1 = w * 64 + 32 + lane;

    // ---- bitonic sort 64 elements in-warp (descending, tie: idx asc) ----
    #pragma unroll
    for (int k = 2; k <= 32; k <<= 1) {
        #pragma unroll
        for (int j = k >> 1; j >= 1; j >>= 1) {
            cmpx(v0, i0, j, ((lane)      & k) == 0);
            cmpx(v1, i1, j, ((lane + 32) & k) == 0);
        }
    }
    // k = 64 level: j=32 is a register swap
    if (!tfirst(v0, i0, v1, i1)) {
        float tv = v0; v0 = v1; v1 = tv;
        int   ti = i0; i0 = i1; i1 = ti;
    }
    #pragma unroll
    for (int j = 16; j >= 1; j >>= 1) { cmpx(v0, i0, j, true); cmpx(v1, i1, j, true); }

    sv[w * 64 + lane] = v0;       si[w * 64 + lane] = i0;
    sv[w * 64 + 32 + lane] = v1;  si[w * 64 + 32 + lane] = i1;
    __syncthreads();

    // ---- 5 merge rounds: keep top-64 of pairs of sorted-desc 64-lists ----
    #pragma unroll
    for (int t = 0; t < 5; t++) {
        const int nw = 16 >> t;
        if (w < nw) {
            const int la = 2 * w, lb = 2 * w + 1;
            float a0 = sv[la * 64 + lane];       int a0i = si[la * 64 + lane];
            float a1 = sv[la * 64 + 32 + lane];  int a1i = si[la * 64 + 32 + lane];
            float b0 = sv[lb * 64 + lane];       int b0i = si[lb * 64 + lane];
            float b1 = sv[lb * 64 + 32 + lane];  int b1i = si[lb * 64 + 32 + lane];
            // C[e] = totalmax(A[e], B[63-e])
            float m0 = __shfl_xor_sync(0xffffffffu, b1, 31);
            int  m0i = __shfl_xor_sync(0xffffffffu, b1i, 31);
            float m1 = __shfl_xor_sync(0xffffffffu, b0, 31);
            int  m1i = __shfl_xor_sync(0xffffffffu, b0i, 31);
            if (!tfirst(a0, a0i, m0, m0i)) { a0 = m0; a0i = m0i; }
            if (!tfirst(a1, a1i, m1, m1i)) { a1 = m1; a1i = m1i; }
            // bitonic merge, descending
            if (!tfirst(a0, a0i, a1, a1i)) {
                float tv = a0; a0 = a1; a1 = tv;
                int   ti = a0i; a0i = a1i; a1i = ti;
            }
            #pragma unroll
            for (int j = 16; j >= 1; j >>= 1) { cmpx(a0, a0i, j, true); cmpx(a1, a1i, j, true); }
            sv[w * 64 + lane] = a0;       si[w * 64 + lane] = a0i;
            sv[w * 64 + 32 + lane] = a1;  si[w * 64 + 32 + lane] = a1i;
        }
        __syncthreads();
    }

    if (tid < K) {
        float v  = sv[tid];
        int   id = si[tid];
        out[b * K + tid]         = v;           // topk_vals
        out[B * K + b * K + tid] = (float)id;   // topk_idx
        g_vals[b * K + tid] = v;
        g_idx [b * K + tid] = id;
        g_pv  [b * N + id]  = v;
    }
}

// ---------------------------------------------------------------------------
// Kernel 2: fused M + frob.
//   blockIdx.x < 128 : M tile — M[b,i,j] = pv[b][i]*pv[b][j], 16 rows/tile,
//                      streaming float4 stores (512 MiB, HBM write roofline).
//   blockIdx.x == 128: frob for batch b — rides free under M's store traffic.
// ---------------------------------------------------------------------------
__global__ __launch_bounds__(256)
void M_frob_kernel(const float* __restrict__ U,
                   float* __restrict__ out,       // base of output
                   float* __restrict__ outM) {    // out + 3*B*K
    const int b   = blockIdx.y;
    const int tid = threadIdx.x;

    if (blockIdx.x < 128) {
        __shared__ float s_pv[N];
        const int tile = blockIdx.x;    // 16 rows per tile

        const float4* pv4 = reinterpret_cast<const float4*>(g_pv + b * N);
        float4* s4 = reinterpret_cast<float4*>(s_pv);
        for (int q = tid; q < N / 4; q += 256) s4[q] = pv4[q];
        __syncthreads();

        float4* out4 = reinterpret_cast<float4*>(outM);
        #pragma unroll
        for (int ir = 0; ir < 16; ir++) {
            const int i = tile * 16 + ir;
            const float pvi = s_pv[i];
            const size_t base = ((size_t)b * N + i) * (N / 4);
            #pragma unroll
            for (int jj = 0; jj < 2; jj++) {
                const int j4 = tid + jj * 256;
                float4 v = s4[j4];
                float4 o = make_float4(pvi * v.x, pvi * v.y, pvi * v.z, pvi * v.w);
                __stcs(&out4[base + j4], o);
            }
        }
    } else {
        // ---- frob: 8 warps; warp w handles channels w*8 .. w*8+7; lane = r
        __shared__ float s_vals[K];
        __shared__ int   s_idx[K];
        if (tid < K) { s_vals[tid] = g_vals[b * K + tid]; s_idx[tid] = g_idx[b * K + tid]; }
        __syncthreads();

        const int lane = tid & 31;
        const int w    = tid >> 5;   // 0..7
        #pragma unroll
        for (int cc = 0; cc < 8; cc++) {
            const int c = w * 8 + cc;
            const float* Uc = U + (size_t)c * N * R;
            float au = 0.0f;
            #pragma unroll 8
            for (int k = 0; k < K; k++)
                au = fmaf(s_vals[k], Uc[(size_t)s_idx[k] * R + lane], au);
            float sq = au * au;
            #pragma unroll
            for (int o = 16; o > 0; o >>= 1)
                sq += __shfl_xor_sync(0xffffffffu, sq, o);
            if (lane == 0) out[2 * B * K + b * C + c] = sq / (float)(K * R);
        }
    }
}

extern "C" void kernel_launch(void* const* d_in, const int* in_sizes, int n_in,
                              void* d_out, int out_size) {
    const float* acc = (const float*)d_in[0];   // [B, N] float32
    const float* U   = (const float*)d_in[1];   // [C, N, R] float32
    float* out  = (float*)d_out;
    float* outM = out + 3 * B * K;

    topk_kernel<<<B, 1024>>>(acc, out);
    M_frob_kernel<<<dim3(129, B), 256>>>(U, out, outM);
}

// round 5
// speedup vs baseline: 1.5072x; 1.5072x over previous
#include <cuda_runtime.h>

#define B 32
#define N 2048
#define C 64
#define R 32
#define K 64

__device__ float g_pv[B * N];     // dense top-k vector per batch
__device__ float g_vals[B * K];
__device__ int   g_idx[B * K];

// total-order "a before b" in descending-value, ascending-index order
__device__ __forceinline__ bool tfirst(float va, int ia, float vb, int ib) {
    return (va > vb) || (va == vb && ia < ib);
}

// shuffle compare-exchange; partner differs in lane bit j
__device__ __forceinline__ void cmpx(float& v, int& i, int j, bool desc) {
    float ov = __shfl_xor_sync(0xffffffffu, v, j);
    int   oi = __shfl_xor_sync(0xffffffffu, i, j);
    bool lower = ((threadIdx.x & 31 & j) == 0);
    bool mine_first = tfirst(v, i, ov, oi);
    if (mine_first != (lower == desc)) { v = ov; i = oi; }
}

// ---------------------------------------------------------------------------
// Kernel 1: warp-register bitonic top-K + pv scatter. One block per batch row.
// ---------------------------------------------------------------------------
__global__ __launch_bounds__(1024)
void topk_kernel(const float* __restrict__ acc, float* __restrict__ out) {
    __shared__ float sv[N];
    __shared__ int   si[N];
    const int b    = blockIdx.x;
    const int tid  = threadIdx.x;
    const int lane = tid & 31;
    const int w    = tid >> 5;           // warp 0..31

    // zero pv row (independent of the sort)
    g_pv[b * N + tid] = 0.0f;
    g_pv[b * N + tid + 1024] = 0.0f;

    // ---- load chunk w: elements e0=lane, e1=lane+32 of a 64-elem list ----
    const float* row = acc + b * N;
    float v0 = row[w * 64 + lane];        int i0 = w * 64 + lane;
    float v1 = row[w * 64 + 32 + lane];   int i1 = w * 64 + 32 + lane;

    // ---- bitonic sort 64 elements in-warp (descending, tie: idx asc) ----
    #pragma unroll
    for (int k = 2; k <= 32; k <<= 1) {
        #pragma unroll
        for (int j = k >> 1; j >= 1; j >>= 1) {
            cmpx(v0, i0, j, ((lane)      & k) == 0);
            cmpx(v1, i1, j, ((lane + 32) & k) == 0);
        }
    }
    // k = 64 level: j=32 is a register swap
    if (!tfirst(v0, i0, v1, i1)) {
        float tv = v0; v0 = v1; v1 = tv;
        int   ti = i0; i0 = i1; i1 = ti;
    }
    #pragma unroll
    for (int j = 16; j >= 1; j >>= 1) { cmpx(v0, i0, j, true); cmpx(v1, i1, j, true); }

    sv[w * 64 + lane] = v0;       si[w * 64 + lane] = i0;
    sv[w * 64 + 32 + lane] = v1;  si[w * 64 + 32 + lane] = i1;
    __syncthreads();

    // ---- 5 merge rounds: keep top-64 of pairs of sorted-desc 64-lists ----
    #pragma unroll
    for (int t = 0; t < 5; t++) {
        const int nw = 16 >> t;
        if (w < nw) {
            const int la = 2 * w, lb = 2 * w + 1;
            float a0 = sv[la * 64 + lane];       int a0i = si[la * 64 + lane];
            float a1 = sv[la * 64 + 32 + lane];  int a1i = si[la * 64 + 32 + lane];
            float b0 = sv[lb * 64 + lane];       int b0i = si[lb * 64 + lane];
            float b1 = sv[lb * 64 + 32 + lane];  int b1i = si[lb * 64 + 32 + lane];
            // C[e] = totalmax(A[e], B[63-e])
            float m0 = __shfl_xor_sync(0xffffffffu, b1, 31);
            int  m0i = __shfl_xor_sync(0xffffffffu, b1i, 31);
            float m1 = __shfl_xor_sync(0xffffffffu, b0, 31);
            int  m1i = __shfl_xor_sync(0xffffffffu, b0i, 31);
            if (!tfirst(a0, a0i, m0, m0i)) { a0 = m0; a0i = m0i; }
            if (!tfirst(a1, a1i, m1, m1i)) { a1 = m1; a1i = m1i; }
            // bitonic merge, descending
            if (!tfirst(a0, a0i, a1, a1i)) {
                float tv = a0; a0 = a1; a1 = tv;
                int   ti = a0i; a0i = a1i; a1i = ti;
            }
            #pragma unroll
            for (int j = 16; j >= 1; j >>= 1) { cmpx(a0, a0i, j, true); cmpx(a1, a1i, j, true); }
            sv[w * 64 + lane] = a0;       si[w * 64 + lane] = a0i;
            sv[w * 64 + 32 + lane] = a1;  si[w * 64 + 32 + lane] = a1i;
        }
        __syncthreads();
    }

    if (tid < K) {
        float v  = sv[tid];
        int   id = si[tid];
        out[b * K + tid]         = v;           // topk_vals
        out[B * K + b * K + tid] = (float)id;   // topk_idx
        g_vals[b * K + tid] = v;
        g_idx [b * K + tid] = id;
        g_pv  [b * N + id]  = v;
    }
}

// ---------------------------------------------------------------------------
// Kernel 2: frob — one warp per (channel, batch). grid (C, B), 2048 warps.
// Topk vals/idx held in registers, broadcast per-k via shuffle (no smem).
// ---------------------------------------------------------------------------
__global__ __launch_bounds__(32)
void frob_kernel(const float* __restrict__ U, float* __restrict__ out) {
    const int c = blockIdx.x;
    const int b = blockIdx.y;
    const int r = threadIdx.x;   // lane = rank index

    // lane r holds entries r and r+32 of the top-64 list
    float v0 = g_vals[b * K + r];
    float v1 = g_vals[b * K + 32 + r];
    int   i0 = g_idx [b * K + r];
    int   i1 = g_idx [b * K + 32 + r];

    const float* Uc = U + (size_t)c * N * R;
    float au = 0.0f;
    #pragma unroll
    for (int k = 0; k < 32; k++) {
        float vk = __shfl_sync(0xffffffffu, v0, k);
        int   ik = __shfl_sync(0xffffffffu, i0, k);
        au = fmaf(vk, __ldg(Uc + (size_t)ik * R + r), au);
    }
    #pragma unroll
    for (int k = 0; k < 32; k++) {
        float vk = __shfl_sync(0xffffffffu, v1, k);
        int   ik = __shfl_sync(0xffffffffu, i1, k);
        au = fmaf(vk, __ldg(Uc + (size_t)ik * R + r), au);
    }

    float sq = au * au;
    #pragma unroll
    for (int o = 16; o > 0; o >>= 1)
        sq += __shfl_xor_sync(0xffffffffu, sq, o);
    if (r == 0) out[2 * B * K + b * C + c] = sq / (float)(K * R);
}

// ---------------------------------------------------------------------------
// Kernel 3: M[b,i,j] = pv[b][i] * pv[b][j] — exact R2 version (proven 76.8us,
// 78.4% DRAM). Do not touch.
// ---------------------------------------------------------------------------
__global__ __launch_bounds__(256)
void M_kernel(float* __restrict__ outM) {
    __shared__ float s_pv[N];
    const int b    = blockIdx.y;
    const int tile = blockIdx.x;    // 16 rows per tile
    const int tid  = threadIdx.x;

    const float4* pv4 = reinterpret_cast<const float4*>(g_pv + b * N);
    float4* s4 = reinterpret_cast<float4*>(s_pv);
    for (int q = tid; q < N / 4; q += 256) s4[q] = pv4[q];
    __syncthreads();

    float4* out4 = reinterpret_cast<float4*>(outM);
    #pragma unroll
    for (int ir = 0; ir < 16; ir++) {
        const int i = tile * 16 + ir;
        const float pvi = s_pv[i];
        const size_t base = ((size_t)b * N + i) * (N / 4);
        #pragma unroll
        for (int jj = 0; jj < 2; jj++) {
            const int j4 = tid + jj * 256;
            float4 v = s4[j4];
            float4 o = make_float4(pvi * v.x, pvi * v.y, pvi * v.z, pvi * v.w);
            __stcs(&out4[base + j4], o);
        }
    }
}

extern "C" void kernel_launch(void* const* d_in, const int* in_sizes, int n_in,
                              void* d_out, int out_size) {
    const float* acc = (const float*)d_in[0];   // [B, N] float32
    const float* U   = (const float*)d_in[1];   // [C, N, R] float32
    float* out  = (float*)d_out;
    float* outM = out + 3 * B * K;

    topk_kernel<<<B, 1024>>>(acc, out);
    frob_kernel<<<dim3(C, B), 32>>>(U, out);
    M_kernel<<<dim3(N / 16, B), 256>>>(outM);
}

// round 6
// speedup vs baseline: 1.5643x; 1.0378x over previous
#include <cuda_runtime.h>

typedef unsigned long long u64;
typedef unsigned int u32;

#define B 32
#define N 2048
#define C 64
#define R 32
#define K 64

__device__ float g_pv[B * N];     // dense top-k vector per batch
__device__ float g_vals[B * K];
__device__ int   g_idx[B * K];

// Monotone key: descending value, ascending index, as one u64 (bigger = first).
__device__ __forceinline__ u64 make_key(float v, int idx) {
    u32 u = __float_as_uint(v);
    u = (u & 0x80000000u) ? ~u : (u | 0x80000000u);   // order-preserving f32->u32
    return ((u64)u << 32) | (u32)(N - 1 - idx);       // low word: smaller idx wins
}

// compare-exchange on packed keys; partner differs in lane bit j
__device__ __forceinline__ void cmpx64(u64& k, int j, bool desc) {
    u64 o = __shfl_xor_sync(0xffffffffu, k, j);
    bool keep_big = (((threadIdx.x & 31) & j) == 0) == desc;
    k = ((k > o) == keep_big) ? k : o;
}

// ---------------------------------------------------------------------------
// Kernel 1: warp-register bitonic top-K on packed u64 keys + pv scatter.
// One block per batch row, 1024 threads (2 keys/thread).
// ---------------------------------------------------------------------------
__global__ __launch_bounds__(1024)
void topk_kernel(const float* __restrict__ acc, float* __restrict__ out) {
    __shared__ u64 sk[N];
    const int b    = blockIdx.x;
    const int tid  = threadIdx.x;
    const int lane = tid & 31;
    const int w    = tid >> 5;           // warp 0..31

    // zero pv row (independent of the sort)
    g_pv[b * N + tid] = 0.0f;
    g_pv[b * N + tid + 1024] = 0.0f;

    // ---- load chunk w: elements e0=lane, e1=lane+32 of a 64-elem list ----
    const float* row = acc + b * N;
    u64 k0 = make_key(row[w * 64 + lane],      w * 64 + lane);
    u64 k1 = make_key(row[w * 64 + 32 + lane], w * 64 + 32 + lane);

    // ---- bitonic sort 64 keys in-warp (descending) ----
    #pragma unroll
    for (int k = 2; k <= 32; k <<= 1) {
        #pragma unroll
        for (int j = k >> 1; j >= 1; j >>= 1) {
            cmpx64(k0, j, ((lane)      & k) == 0);
            cmpx64(k1, j, ((lane + 32) & k) == 0);
        }
    }
    // k = 64 level: j=32 is a register swap (descending)
    if (!(k0 > k1)) { u64 t = k0; k0 = k1; k1 = t; }
    #pragma unroll
    for (int j = 16; j >= 1; j >>= 1) { cmpx64(k0, j, true); cmpx64(k1, j, true); }

    sk[w * 64 + lane]      = k0;
    sk[w * 64 + 32 + lane] = k1;
    __syncthreads();

    // ---- 5 merge rounds: keep top-64 of pairs of sorted-desc 64-lists ----
    #pragma unroll
    for (int t = 0; t < 5; t++) {
        const int nw = 16 >> t;
        if (w < nw) {
            const int la = 2 * w, lb = 2 * w + 1;
            u64 a0 = sk[la * 64 + lane];
            u64 a1 = sk[la * 64 + 32 + lane];
            u64 b0 = sk[lb * 64 + lane];
            u64 b1 = sk[lb * 64 + 32 + lane];
            // C[e] = max(A[e], B[63-e])
            u64 m0 = __shfl_xor_sync(0xffffffffu, b1, 31);
            u64 m1 = __shfl_xor_sync(0xffffffffu, b0, 31);
            if (m0 > a0) a0 = m0;
            if (m1 > a1) a1 = m1;
            // bitonic merge, descending
            if (!(a0 > a1)) { u64 tt = a0; a0 = a1; a1 = tt; }
            #pragma unroll
            for (int j = 16; j >= 1; j >>= 1) { cmpx64(a0, j, true); cmpx64(a1, j, true); }
            sk[w * 64 + lane]      = a0;
            sk[w * 64 + 32 + lane] = a1;
        }
        __syncthreads();
    }

    if (tid < K) {
        u64 kk = sk[tid];
        int id = (N - 1) - (int)(kk & 0xffffffffu);
        u32 hu = (u32)(kk >> 32);
        u32 fb = (hu & 0x80000000u) ? (hu ^ 0x80000000u) : ~hu;
        float v = __uint_as_float(fb);
        out[b * K + tid]         = v;           // topk_vals
        out[B * K + b * K + tid] = (float)id;   // topk_idx
        g_vals[b * K + tid] = v;
        g_idx [b * K + tid] = id;
        g_pv  [b * N + id]  = v;
    }
}

// ---------------------------------------------------------------------------
// Kernel 2: frob — one warp per (channel, batch). grid (C, B), 2048 warps.
// Runs CONCURRENTLY with M_kernel on a side stream.
// ---------------------------------------------------------------------------
__global__ __launch_bounds__(32)
void frob_kernel(const float* __restrict__ U, float* __restrict__ out) {
    const int c = blockIdx.x;
    const int b = blockIdx.y;
    const int r = threadIdx.x;   // lane = rank index

    float v0 = g_vals[b * K + r];
    float v1 = g_vals[b * K + 32 + r];
    int   i0 = g_idx [b * K + r];
    int   i1 = g_idx [b * K + 32 + r];

    const float* Uc = U + (size_t)c * N * R;
    float au = 0.0f;
    #pragma unroll
    for (int k = 0; k < 32; k++) {
        float vk = __shfl_sync(0xffffffffu, v0, k);
        int   ik = __shfl_sync(0xffffffffu, i0, k);
        au = fmaf(vk, __ldg(Uc + (size_t)ik * R + r), au);
    }
    #pragma unroll
    for (int k = 0; k < 32; k++) {
        float vk = __shfl_sync(0xffffffffu, v1, k);
        int   ik = __shfl_sync(0xffffffffu, i1, k);
        au = fmaf(vk, __ldg(Uc + (size_t)ik * R + r), au);
    }

    float sq = au * au;
    #pragma unroll
    for (int o = 16; o > 0; o >>= 1)
        sq += __shfl_xor_sync(0xffffffffu, sq, o);
    if (r == 0) out[2 * B * K + b * C + c] = sq / (float)(K * R);
}

// ---------------------------------------------------------------------------
// Kernel 3: M[b,i,j] = pv[b][i] * pv[b][j] — exact R2 version (76.8us,
// 78.4% DRAM). Do not touch.
// ---------------------------------------------------------------------------
__global__ __launch_bounds__(256)
void M_kernel(float* __restrict__ outM) {
    __shared__ float s_pv[N];
    const int b    = blockIdx.y;
    const int tile = blockIdx.x;    // 16 rows per tile
    const int tid  = threadIdx.x;

    const float4* pv4 = reinterpret_cast<const float4*>(g_pv + b * N);
    float4* s4 = reinterpret_cast<float4*>(s_pv);
    for (int q = tid; q < N / 4; q += 256) s4[q] = pv4[q];
    __syncthreads();

    float4* out4 = reinterpret_cast<float4*>(outM);
    #pragma unroll
    for (int ir = 0; ir < 16; ir++) {
        const int i = tile * 16 + ir;
        const float pvi = s_pv[i];
        const size_t base = ((size_t)b * N + i) * (N / 4);
        #pragma unroll
        for (int jj = 0; jj < 2; jj++) {
            const int j4 = tid + jj * 256;
            float4 v = s4[j4];
            float4 o = make_float4(pvi * v.x, pvi * v.y, pvi * v.z, pvi * v.w);
            __stcs(&out4[base + j4], o);
        }
    }
}

// Side stream + events, created once at static init (host resources only —
// no device memory, so allocation guards are satisfied).
static cudaStream_t g_s_frob;
static cudaEvent_t  g_ev_topk, g_ev_frob;
struct _StreamInit {
    _StreamInit() {
        cudaStreamCreateWithFlags(&g_s_frob, cudaStreamNonBlocking);
        cudaEventCreateWithFlags(&g_ev_topk, cudaEventDisableTiming);
        cudaEventCreateWithFlags(&g_ev_frob, cudaEventDisableTiming);
    }
};
static _StreamInit g_stream_init;

extern "C" void kernel_launch(void* const* d_in, const int* in_sizes, int n_in,
                              void* d_out, int out_size) {
    const float* acc = (const float*)d_in[0];   // [B, N] float32
    const float* U   = (const float*)d_in[1];   // [C, N, R] float32
    float* out  = (float*)d_out;
    float* outM = out + 3 * B * K;

    topk_kernel<<<B, 1024>>>(acc, out);
    // fork: frob runs concurrently with M on a side stream
    cudaEventRecord(g_ev_topk, 0);
    cudaStreamWaitEvent(g_s_frob, g_ev_topk, 0);
    frob_kernel<<<dim3(C, B), 32, 0, g_s_frob>>>(U, out);
    cudaEventRecord(g_ev_frob, g_s_frob);

    M_kernel<<<dim3(N / 16, B), 256>>>(outM);
    // join
    cudaStreamWaitEvent(0, g_ev_frob, 0);
}

// round 7
// speedup vs baseline: 1.5838x; 1.0125x over previous
#include <cuda_runtime.h>

typedef unsigned long long u64;
typedef unsigned int u32;

#define B 32
#define N 2048
#define C 64
#define R 32
#define K 64

__device__ float g_pv[B * N];     // dense top-k vector per batch
__device__ float g_vals[B * K];
__device__ int   g_idx[B * K];

// Monotone key: descending value, ascending index, as one u64 (bigger = first).
__device__ __forceinline__ u64 make_key(float v, int idx) {
    u32 u = __float_as_uint(v);
    u = (u & 0x80000000u) ? ~u : (u | 0x80000000u);   // order-preserving f32->u32
    return ((u64)u << 32) | (u32)(N - 1 - idx);       // low word: smaller idx wins
}

// compare-exchange on packed keys; partner differs in lane bit j
__device__ __forceinline__ void cmpx64(u64& k, int j, bool desc) {
    u64 o = __shfl_xor_sync(0xffffffffu, k, j);
    bool keep_big = (((threadIdx.x & 31) & j) == 0) == desc;
    k = ((k > o) == keep_big) ? k : o;
}

// ---------------------------------------------------------------------------
// Kernel 1: warp-register bitonic top-K on packed u64 keys + pv scatter.
// One block per batch row, 1024 threads (2 keys/thread).
// ---------------------------------------------------------------------------
__global__ __launch_bounds__(1024)
void topk_kernel(const float* __restrict__ acc, float* __restrict__ out) {
    __shared__ u64 sk[N];
    const int b    = blockIdx.x;
    const int tid  = threadIdx.x;
    const int lane = tid & 31;
    const int w    = tid >> 5;           // warp 0..31

    // zero pv row (independent of the sort)
    g_pv[b * N + tid] = 0.0f;
    g_pv[b * N + tid + 1024] = 0.0f;

    // ---- load chunk w: elements e0=lane, e1=lane+32 of a 64-elem list ----
    const float* row = acc + b * N;
    u64 k0 = make_key(row[w * 64 + lane],      w * 64 + lane);
    u64 k1 = make_key(row[w * 64 + 32 + lane], w * 64 + 32 + lane);

    // ---- bitonic sort 64 keys in-warp (descending) ----
    #pragma unroll
    for (int k = 2; k <= 32; k <<= 1) {
        #pragma unroll
        for (int j = k >> 1; j >= 1; j >>= 1) {
            cmpx64(k0, j, ((lane)      & k) == 0);
            cmpx64(k1, j, ((lane + 32) & k) == 0);
        }
    }
    // k = 64 level: j=32 is a register swap (descending)
    if (!(k0 > k1)) { u64 t = k0; k0 = k1; k1 = t; }
    #pragma unroll
    for (int j = 16; j >= 1; j >>= 1) { cmpx64(k0, j, true); cmpx64(k1, j, true); }

    sk[w * 64 + lane]      = k0;
    sk[w * 64 + 32 + lane] = k1;
    __syncthreads();

    // ---- 5 merge rounds: keep top-64 of pairs of sorted-desc 64-lists.
    // Final round (t=4): warp 0 holds the answer in registers -> emit directly.
    u64 f0 = 0, f1 = 0;
    #pragma unroll
    for (int t = 0; t < 5; t++) {
        const int nw = 16 >> t;
        if (w < nw) {
            const int la = 2 * w, lb = 2 * w + 1;
            u64 a0 = sk[la * 64 + lane];
            u64 a1 = sk[la * 64 + 32 + lane];
            u64 b0 = sk[lb * 64 + lane];
            u64 b1 = sk[lb * 64 + 32 + lane];
            // C[e] = max(A[e], B[63-e])
            u64 m0 = __shfl_xor_sync(0xffffffffu, b1, 31);
            u64 m1 = __shfl_xor_sync(0xffffffffu, b0, 31);
            if (m0 > a0) a0 = m0;
            if (m1 > a1) a1 = m1;
            // bitonic merge, descending
            if (!(a0 > a1)) { u64 tt = a0; a0 = a1; a1 = tt; }
            #pragma unroll
            for (int j = 16; j >= 1; j >>= 1) { cmpx64(a0, j, true); cmpx64(a1, j, true); }
            if (t < 4) {
                sk[w * 64 + lane]      = a0;
                sk[w * 64 + 32 + lane] = a1;
            } else { f0 = a0; f1 = a1; }
        }
        if (t < 4) __syncthreads();
    }

    // ---- emit from warp 0 registers: entries lane and lane+32 ----
    if (w == 0) {
        #pragma unroll
        for (int h = 0; h < 2; h++) {
            u64 kk = h ? f1 : f0;
            int pos = lane + h * 32;
            int id = (N - 1) - (int)(kk & 0xffffffffu);
            u32 hu = (u32)(kk >> 32);
            u32 fb = (hu & 0x80000000u) ? (hu ^ 0x80000000u) : ~hu;
            float v = __uint_as_float(fb);
            out[b * K + pos]         = v;           // topk_vals
            out[B * K + b * K + pos] = (float)id;   // topk_idx
            g_vals[b * K + pos] = v;
            g_idx [b * K + pos] = id;
            g_pv  [b * N + id]  = v;
        }
    }

    // PDL: allow the dependent M_kernel to begin once all CTAs reach here.
    asm volatile("griddepcontrol.launch_dependents;");
}

// ---------------------------------------------------------------------------
// Kernel 2: frob — one warp per (channel, batch). grid (C, B), 2048 warps.
// Runs CONCURRENTLY with M_kernel on a side stream.
// ---------------------------------------------------------------------------
__global__ __launch_bounds__(32)
void frob_kernel(const float* __restrict__ U, float* __restrict__ out) {
    const int c = blockIdx.x;
    const int b = blockIdx.y;
    const int r = threadIdx.x;   // lane = rank index

    float v0 = g_vals[b * K + r];
    float v1 = g_vals[b * K + 32 + r];
    int   i0 = g_idx [b * K + r];
    int   i1 = g_idx [b * K + 32 + r];

    const float* Uc = U + (size_t)c * N * R;
    float au = 0.0f;
    #pragma unroll
    for (int k = 0; k < 32; k++) {
        float vk = __shfl_sync(0xffffffffu, v0, k);
        int   ik = __shfl_sync(0xffffffffu, i0, k);
        au = fmaf(vk, __ldg(Uc + (size_t)ik * R + r), au);
    }
    #pragma unroll
    for (int k = 0; k < 32; k++) {
        float vk = __shfl_sync(0xffffffffu, v1, k);
        int   ik = __shfl_sync(0xffffffffu, i1, k);
        au = fmaf(vk, __ldg(Uc + (size_t)ik * R + r), au);
    }

    float sq = au * au;
    #pragma unroll
    for (int o = 16; o > 0; o >>= 1)
        sq += __shfl_xor_sync(0xffffffffu, sq, o);
    if (r == 0) out[2 * B * K + b * C + c] = sq / (float)(K * R);
}

// ---------------------------------------------------------------------------
// Kernel 3: M[b,i,j] = pv[b][i] * pv[b][j] — R2 store loop (76.8us, 78.4% DRAM),
// now PDL-gated: prologue overlaps topk's tail; wait only before reading pv.
// ---------------------------------------------------------------------------
__global__ __launch_bounds__(256)
void M_kernel(float* __restrict__ outM) {
    __shared__ float s_pv[N];
    const int b    = blockIdx.y;
    const int tile = blockIdx.x;    // 16 rows per tile
    const int tid  = threadIdx.x;

    // PDL: block scheduling + setup already overlapped; now wait for topk data.
    asm volatile("griddepcontrol.wait;" ::: "memory");

    const float4* pv4 = reinterpret_cast<const float4*>(g_pv + b * N);
    float4* s4 = reinterpret_cast<float4*>(s_pv);
    for (int q = tid; q < N / 4; q += 256) s4[q] = pv4[q];
    __syncthreads();

    float4* out4 = reinterpret_cast<float4*>(outM);
    #pragma unroll
    for (int ir = 0; ir < 16; ir++) {
        const int i = tile * 16 + ir;
        const float pvi = s_pv[i];
        const size_t base = ((size_t)b * N + i) * (N / 4);
        #pragma unroll
        for (int jj = 0; jj < 2; jj++) {
            const int j4 = tid + jj * 256;
            float4 v = s4[j4];
            float4 o = make_float4(pvi * v.x, pvi * v.y, pvi * v.z, pvi * v.w);
            __stcs(&out4[base + j4], o);
        }
    }
}

// Side stream + events (host resources only — no device memory).
static cudaStream_t g_s_frob;
static cudaEvent_t  g_ev_topk, g_ev_frob;
struct _StreamInit {
    _StreamInit() {
        cudaStreamCreateWithFlags(&g_s_frob, cudaStreamNonBlocking);
        cudaEventCreateWithFlags(&g_ev_topk, cudaEventDisableTiming);
        cudaEventCreateWithFlags(&g_ev_frob, cudaEventDisableTiming);
    }
};
static _StreamInit g_stream_init;

extern "C" void kernel_launch(void* const* d_in, const int* in_sizes, int n_in,
                              void* d_out, int out_size) {
    const float* acc = (const float*)d_in[0];   // [B, N] float32
    const float* U   = (const float*)d_in[1];   // [C, N, R] float32
    float* out  = (float*)d_out;
    float* outM = out + 3 * B * K;

    topk_kernel<<<B, 1024>>>(acc, out);

    // fork: frob runs concurrently with M on a side stream
    cudaEventRecord(g_ev_topk, 0);
    cudaStreamWaitEvent(g_s_frob, g_ev_topk, 0);
    frob_kernel<<<dim3(C, B), 32, 0, g_s_frob>>>(U, out);
    cudaEventRecord(g_ev_frob, g_s_frob);

    // M with programmatic dependent launch on topk (same stream)
    cudaLaunchConfig_t cfg = {};
    cfg.gridDim  = dim3(N / 16, B);
    cfg.blockDim = dim3(256);
    cfg.dynamicSmemBytes = 0;
    cfg.stream = (cudaStream_t)0;
    cudaLaunchAttribute attr[1];
    attr[0].id = cudaLaunchAttributeProgrammaticStreamSerialization;
    attr[0].val.programmaticStreamSerializationAllowed = 1;
    cfg.attrs = attr;
    cfg.numAttrs = 1;
    cudaLaunchKernelEx(&cfg, M_kernel, outM);

    // join
    cudaStreamWaitEvent((cudaStream_t)0, g_ev_frob, 0);
}